// round 5
// baseline (speedup 1.0000x reference)
#include <cuda_runtime.h>
#include <math.h>

#define B_TOTAL 32768
#define X_DIM   30
#define Y_DIM   30
#define F_DIM   6
#define CELLS   (X_DIM * Y_DIM)      // 900
#define THREADS 256
#define PRE_BLOCKS 113                // 113 * 8 cells = 904 >= 900
#define MAIN_BLOCKS (B_TOTAL / THREADS)  // 128

__device__ float g_S[CELLS];

// ---------------- Kernel 1: precompute S ----------------
// 113 blocks x 256 threads; tid = h*128 + p, 8 cells per block.
__global__ void __launch_bounds__(THREADS)
precompute_S_kernel(const float* __restrict__ succ,
                    const float* __restrict__ w) {
    const int tid  = threadIdx.x;
    const int h    = tid >> 7;
    const int p    = tid & 127;
    const int lane = tid & 31;
    const int w4g  = (tid >> 5) & 3;
    const int cell0 = blockIdx.x * 8 + h * 4;
    const bool valid = cell0 < CELLS;

    const float w0 = __ldg(&w[0]), w1 = __ldg(&w[1]), w2 = __ldg(&w[2]);
    const float w3 = __ldg(&w[3]), w4 = __ldg(&w[4]), w5 = __ldg(&w[5]);

    __shared__ float smax[2][4][4];
    __shared__ float ssum[2][4][4][2];

    float v[4], x[4];
    if (valid) {
        // byte offset = p*21600 + cell0*24 (cell0 % 4 == 0) -> 16B aligned
        const float4* base =
            (const float4*)(succ + (size_t)p * (CELLS * F_DIM) + (size_t)cell0 * F_DIM);
        const float4 q0 = base[0], q1 = base[1], q2 = base[2];
        const float4 q3 = base[3], q4 = base[4], q5 = base[5];

        v[0] = q0.x*w0 + q0.y*w1 + q0.z*w2 + q0.w*w3 + q1.x*w4 + q1.y*w5;
        v[1] = q1.z*w0 + q1.w*w1 + q2.x*w2 + q2.y*w3 + q2.z*w4 + q2.w*w5;
        v[2] = q3.x*w0 + q3.y*w1 + q3.z*w2 + q3.w*w3 + q4.x*w4 + q4.y*w5;
        v[3] = q4.z*w0 + q4.w*w1 + q5.x*w2 + q5.y*w3 + q5.z*w4 + q5.w*w5;

#pragma unroll
        for (int j = 0; j < 4; ++j) x[j] = v[j] / 0.001f;   // match vs / T

#pragma unroll
        for (int j = 0; j < 4; ++j) {
            float mm = x[j];
#pragma unroll
            for (int s = 16; s > 0; s >>= 1)
                mm = fmaxf(mm, __shfl_xor_sync(0xFFFFFFFFu, mm, s));
            if (lane == 0) smax[h][j][w4g] = mm;
        }
    }
    __syncthreads();

    if (valid) {
#pragma unroll
        for (int j = 0; j < 4; ++j) {
            const float mx = fmaxf(fmaxf(smax[h][j][0], smax[h][j][1]),
                                   fmaxf(smax[h][j][2], smax[h][j][3]));
            float e  = __expf(x[j] - mx);
            float ev = e * v[j];
#pragma unroll
            for (int s = 16; s > 0; s >>= 1) {
                e  += __shfl_xor_sync(0xFFFFFFFFu, e,  s);
                ev += __shfl_xor_sync(0xFFFFFFFFu, ev, s);
            }
            if (lane == 0) { ssum[h][j][w4g][0] = e; ssum[h][j][w4g][1] = ev; }
        }
    }
    __syncthreads();

    if (valid && (tid & 127) < 4) {
        const int j = tid & 3;
        const float se  = ssum[h][j][0][0] + ssum[h][j][1][0]
                        + ssum[h][j][2][0] + ssum[h][j][3][0];
        const float sev = ssum[h][j][0][1] + ssum[h][j][1][1]
                        + ssum[h][j][2][1] + ssum[h][j][3][1];
        g_S[cell0 + j] = sev / se;
    }
    __syncthreads();   // all g_S STGs (L2-visible) issued before the trigger

    // Signal dependent kernel: this CTA's work is done.
    asm volatile("griddepcontrol.launch_dependents;" ::: "memory");
}

// ---------------- Kernel 2: per-batch finish (PDL dependent) ----------------
__global__ void __launch_bounds__(THREADS)
main_kernel(const float* __restrict__ phi,
            const float* __restrict__ w,
            float* __restrict__ out) {
    const int b = blockIdx.x * THREADS + threadIdx.x;

    // Pre-sync phase: overlap with kernel 1's execution.
    const float4* ph = (const float4*)(phi + (size_t)b * 20);
    const float4 a0 = ph[0];
    const float4 a1 = ph[1];
    const float4 a2 = ph[2];
    const float4 a3 = ph[3];
    const float4 a4 = ph[4];

    const float w0 = __ldg(&w[0]), w1 = __ldg(&w[1]), w2 = __ldg(&w[2]);
    const float w3 = __ldg(&w[3]), w4 = __ldg(&w[4]), w5 = __ldg(&w[5]);

    const float pr0 = a0.x*w0 + a0.y*w1 + a0.z*w2 + a0.w*w3 + a1.x*w4 + a1.y*w5;
    const float pr1 = a2.z*w0 + a2.w*w1 + a3.x*w2 + a3.y*w3 + a3.z*w4 + a3.w*w5;

    const int is0 = (int)a1.z * Y_DIM + (int)a1.w;
    const int ie0 = (int)a2.x * Y_DIM + (int)a2.y;
    const int is1 = (int)a4.x * Y_DIM + (int)a4.y;
    const int ie1 = (int)a4.z * Y_DIM + (int)a4.w;

    // Wait for kernel 1's grid (g_S fully published).
    asm volatile("griddepcontrol.wait;" ::: "memory");

    const float d0 = pr0 + (__ldcg(&g_S[ie0]) - __ldcg(&g_S[is0]));
    const float d1 = pr1 + (__ldcg(&g_S[ie1]) - __ldcg(&g_S[is1]));

    const float diff = d0 - d1;
    float2 r;
    r.x = 1.0f / (1.0f + __expf(-diff));
    r.y = 1.0f / (1.0f + __expf( diff));
    ((float2*)out)[b] = r;
}

extern "C" void kernel_launch(void* const* d_in, const int* in_sizes, int n_in,
                              void* d_out, int out_size) {
    const float* phi  = (const float*)d_in[0];   // (32768, 2, 10)
    const float* succ = (const float*)d_in[1];   // (128, 30, 30, 6)
    const float* w    = (const float*)d_in[2];   // (6,)
    float* out = (float*)d_out;                  // (32768, 2, 1)

    precompute_S_kernel<<<PRE_BLOCKS, THREADS>>>(succ, w);

    // Dependent launch: may begin while kernel 1 is still running; it
    // self-synchronizes via griddepcontrol.wait before touching g_S.
    cudaLaunchConfig_t cfg = {};
    cfg.gridDim  = dim3(MAIN_BLOCKS);
    cfg.blockDim = dim3(THREADS);
    cfg.dynamicSmemBytes = 0;
    cfg.stream = 0;
    cudaLaunchAttribute attrs[1];
    attrs[0].id = cudaLaunchAttributeProgrammaticStreamSerialization;
    attrs[0].val.programmaticStreamSerializationAllowed = 1;
    cfg.attrs = attrs;
    cfg.numAttrs = 1;
    cudaLaunchKernelEx(&cfg, main_kernel, phi, w, out);
}

// round 6
// speedup vs baseline: 1.4337x; 1.4337x over previous
#include <cuda_runtime.h>
#include <math.h>

#define B_TOTAL 32768
#define X_DIM   30
#define Y_DIM   30
#define F_DIM   6
#define CELLS   (X_DIM * Y_DIM)      // 900
#define THREADS 256
#define PROD_BLOCKS 113               // 113 * 8 cells = 904 >= 900
#define PACK_BLOCKS (B_TOTAL / THREADS)   // 128
#define K1_GRID (PROD_BLOCKS + PACK_BLOCKS)

__device__ float g_S[CELLS];
__device__ uint4 g_pack[B_TOTAL];     // 512KB packed intermediates

// ---------------- Kernel 1: S-table + phi packing (independent halves) ----------------
__global__ void __launch_bounds__(THREADS)
k1_kernel(const float* __restrict__ phi,
          const float* __restrict__ succ,
          const float* __restrict__ w) {
    const int tid = threadIdx.x;
    const int bid = blockIdx.x;

    const float w0 = __ldg(&w[0]), w1 = __ldg(&w[1]), w2 = __ldg(&w[2]);
    const float w3 = __ldg(&w[3]), w4 = __ldg(&w[4]), w5 = __ldg(&w[5]);

    if (bid < PROD_BLOCKS) {
        // ----- S producer: 8 cells per block; tid = h*128 + p -----
        const int h    = tid >> 7;
        const int p    = tid & 127;
        const int lane = tid & 31;
        const int w4g  = (tid >> 5) & 3;
        const int cell0 = bid * 8 + h * 4;
        const bool valid = cell0 < CELLS;

        __shared__ float smax[2][4][4];
        __shared__ float ssum[2][4][4][2];

        float v[4], x[4];
        if (valid) {
            // byte offset = p*21600 + cell0*24 (cell0 % 4 == 0) -> 16B aligned
            const float4* base =
                (const float4*)(succ + (size_t)p * (CELLS * F_DIM) + (size_t)cell0 * F_DIM);
            const float4 q0 = base[0], q1 = base[1], q2 = base[2];
            const float4 q3 = base[3], q4 = base[4], q5 = base[5];

            v[0] = q0.x*w0 + q0.y*w1 + q0.z*w2 + q0.w*w3 + q1.x*w4 + q1.y*w5;
            v[1] = q1.z*w0 + q1.w*w1 + q2.x*w2 + q2.y*w3 + q2.z*w4 + q2.w*w5;
            v[2] = q3.x*w0 + q3.y*w1 + q3.z*w2 + q3.w*w3 + q4.x*w4 + q4.y*w5;
            v[3] = q4.z*w0 + q4.w*w1 + q5.x*w2 + q5.y*w3 + q5.z*w4 + q5.w*w5;

#pragma unroll
            for (int j = 0; j < 4; ++j) x[j] = v[j] / 0.001f;   // match vs / T

#pragma unroll
            for (int j = 0; j < 4; ++j) {
                float mm = x[j];
#pragma unroll
                for (int s = 16; s > 0; s >>= 1)
                    mm = fmaxf(mm, __shfl_xor_sync(0xFFFFFFFFu, mm, s));
                if (lane == 0) smax[h][j][w4g] = mm;
            }
        }
        __syncthreads();

        if (valid) {
#pragma unroll
            for (int j = 0; j < 4; ++j) {
                const float mx = fmaxf(fmaxf(smax[h][j][0], smax[h][j][1]),
                                       fmaxf(smax[h][j][2], smax[h][j][3]));
                float e  = __expf(x[j] - mx);
                float ev = e * v[j];
#pragma unroll
                for (int s = 16; s > 0; s >>= 1) {
                    e  += __shfl_xor_sync(0xFFFFFFFFu, e,  s);
                    ev += __shfl_xor_sync(0xFFFFFFFFu, ev, s);
                }
                if (lane == 0) { ssum[h][j][w4g][0] = e; ssum[h][j][w4g][1] = ev; }
            }
        }
        __syncthreads();

        if (valid && (tid & 127) < 4) {
            const int j = tid & 3;
            const float se  = ssum[h][j][0][0] + ssum[h][j][1][0]
                            + ssum[h][j][2][0] + ssum[h][j][3][0];
            const float sev = ssum[h][j][0][1] + ssum[h][j][1][1]
                            + ssum[h][j][2][1] + ssum[h][j][3][1];
            g_S[cell0 + j] = sev / se;
        }
    } else {
        // ----- phi packer: 256 batch elems per block, no dependency on S -----
        const int b = (bid - PROD_BLOCKS) * THREADS + tid;

        const float4* ph = (const float4*)(phi + (size_t)b * 20);
        const float4 a0 = ph[0];
        const float4 a1 = ph[1];
        const float4 a2 = ph[2];
        const float4 a3 = ph[3];
        const float4 a4 = ph[4];

        const float pr0 = a0.x*w0 + a0.y*w1 + a0.z*w2 + a0.w*w3 + a1.x*w4 + a1.y*w5;
        const float pr1 = a2.z*w0 + a2.w*w1 + a3.x*w2 + a3.y*w3 + a3.z*w4 + a3.w*w5;

        const unsigned is0 = (unsigned)((int)a1.z * Y_DIM + (int)a1.w);
        const unsigned ie0 = (unsigned)((int)a2.x * Y_DIM + (int)a2.y);
        const unsigned is1 = (unsigned)((int)a4.x * Y_DIM + (int)a4.y);
        const unsigned ie1 = (unsigned)((int)a4.z * Y_DIM + (int)a4.w);

        uint4 pk;
        pk.x = __float_as_uint(pr0);
        pk.y = __float_as_uint(pr1);
        pk.z = is0 | (ie0 << 16);
        pk.w = is1 | (ie1 << 16);
        g_pack[b] = pk;
    }
}

// ---------------- Kernel 2: tiny finish (L2-resident inputs) ----------------
__global__ void __launch_bounds__(THREADS)
k2_kernel(float* __restrict__ out) {
    const int b = blockIdx.x * THREADS + threadIdx.x;

    const uint4 pk = g_pack[b];
    const float pr0 = __uint_as_float(pk.x);
    const float pr1 = __uint_as_float(pk.y);
    const int is0 = pk.z & 0xFFFF;
    const int ie0 = pk.z >> 16;
    const int is1 = pk.w & 0xFFFF;
    const int ie1 = pk.w >> 16;

    const float d0 = pr0 + (g_S[ie0] - g_S[is0]);
    const float d1 = pr1 + (g_S[ie1] - g_S[is1]);

    const float diff = d0 - d1;
    float2 r;
    r.x = 1.0f / (1.0f + __expf(-diff));
    r.y = 1.0f / (1.0f + __expf( diff));
    ((float2*)out)[b] = r;
}

extern "C" void kernel_launch(void* const* d_in, const int* in_sizes, int n_in,
                              void* d_out, int out_size) {
    const float* phi  = (const float*)d_in[0];   // (32768, 2, 10)
    const float* succ = (const float*)d_in[1];   // (128, 30, 30, 6)
    const float* w    = (const float*)d_in[2];   // (6,)
    float* out = (float*)d_out;                  // (32768, 2, 1)

    k1_kernel<<<K1_GRID, THREADS>>>(phi, succ, w);
    k2_kernel<<<B_TOTAL / THREADS, THREADS>>>(out);
}